// round 6
// baseline (speedup 1.0000x reference)
#include <cuda_runtime.h>

#define BB 64
#define CC 3
#define RR 64
#define CL 64
#define EE 64
#define HH 32
#define LL 3
#define VV 258
#define GG 96   // 3*H

typedef unsigned long long u64;

// ---------------- scratch (device globals; no allocation) ----------------
__device__ float g_giemb[CC * VV * GG];               // [c][v][g] = Wih0[:, :64] @ embed
__device__ float g_wpk[CC * 288 * 96];                // per-thread packed rows: wi[32], wh[32], wq[32]
__device__ float g_bpk[CC * 288 * 4];                 // per-thread bias: (bi, bh, pv, 0)
__device__ float g_hid[(size_t)BB * CC * RR * CL * HH];  // all hidden outputs

// ---------------- helpers ----------------
#define FMA2(acc, a, b) asm("fma.rn.f32x2 %0, %1, %2, %0;" : "+l"(acc) : "l"(a), "l"(b))

__device__ __forceinline__ float sum2(u64 a) {
    float lo = __uint_as_float((unsigned)(a & 0xffffffffull));
    float hi = __uint_as_float((unsigned)(a >> 32));
    return lo + hi;
}
__device__ __forceinline__ void cpa16(void* dst, const void* src) {
    unsigned sd = (unsigned)__cvta_generic_to_shared(dst);
    asm volatile("cp.async.ca.shared.global [%0], [%1], 16;" :: "r"(sd), "l"(src) : "memory");
}
// fast sigmoid via MUFU.TANH (used for r,z gates only)
__device__ __forceinline__ float sigm_a(float x) {
    float t;
    asm("tanh.approx.f32 %0, %1;" : "=f"(t) : "f"(0.5f * x));
    return fmaf(0.5f, t, 0.5f);
}
// accurate tanh for the n gate (signal path)
__device__ __forceinline__ float tanh_f(float x) {
    float e = __expf(-2.f * x);
    return __fdividef(2.f, 1.f + e) - 1.f;
}

// ---------------- dynamic shared layout (2 batches per CTA) ----------------
struct SmemT {
    float row[2][CL][HH];          // [nb][t][g]  prev-row layer-2 outputs (single buffer, skew-safe)
    float pout[2][2][CL][HH];      // [nb][buf][t][g]  prev-channel outputs (double buffered)
    float h[2][LL][HH];            // [nb][l][g]  per-layer hidden
    float rz[2][LL][64];           // sigma(r), sigma(z) finished gate values
    float2 n2[2][LL][HH];          // (i_n, h_n) pairs
    int idx[2][2][CL];             // x indices (double buffered)
};

// ---------------- precompute kernels ----------------
__global__ void prep_giemb(const float* __restrict__ Wih0, const float* __restrict__ embed) {
    int idx = blockIdx.x * blockDim.x + threadIdx.x;
    if (idx >= CC * VV * GG) return;
    int c = idx / (VV * GG);
    int rem = idx % (VV * GG);
    int v = rem / GG;
    int g = rem % GG;
    const float* wr = Wih0 + (c * GG + g) * (EE + 1);
    const float* em = embed + (c * VV + v) * EE;
    float acc = 0.f;
#pragma unroll
    for (int e = 0; e < EE; e++) acc += wr[e] * em[e];
    g_giemb[idx] = acc;
}

__global__ void prep_wpk2(const float* __restrict__ Wih0, const float* __restrict__ Wih_rest,
                          const float* __restrict__ Whh, const float* __restrict__ W_h2e,
                          const float* __restrict__ W_ad) {
    int idx = blockIdx.x * blockDim.x + threadIdx.x;
    if (idx >= CC * 288 * 96) return;
    int c = idx / (288 * 96);
    int rem = idx % (288 * 96);
    int t = rem / 96;
    int j = rem % 96;
    int s = j / 32;
    int k = j % 32;
    int l = t / 96;
    int g = t % 96;
    float val = 0.f;
    if (s == 0) {
        if (l == 0) {
            const float* wr = Wih0 + (c * GG + g) * (EE + 1);
            for (int e = 0; e <= EE; e++)
                val += wr[e] * W_h2e[(c * (EE + 1) + e) * HH + k];
        } else {
            val = Wih_rest[((c * (LL - 1) + (l - 1)) * GG + g) * HH + k];
        }
    } else if (s == 1) {
        val = Whh[((c * LL + l) * GG + g) * HH + k];
    } else {
        if (l == 0 && c > 0) {
            const float* wr = Wih0 + (c * GG + g) * (EE + 1);
            for (int e = 0; e <= EE; e++)
                val += wr[e] * W_ad[((c - 1) * (EE + 1) + e) * HH + k];
        }
    }
    g_wpk[idx] = val;
}

__global__ void prep_bpk2(const float* __restrict__ Wih0, const float* __restrict__ bih,
                          const float* __restrict__ bhh, const float* __restrict__ b_h2e,
                          const float* __restrict__ b_ad) {
    int idx = blockIdx.x * blockDim.x + threadIdx.x;
    if (idx >= CC * 288) return;
    int c = idx / 288;
    int t = idx % 288;
    int l = t / 96;
    int g = t % 96;
    float bi, bh, pv;
    if (l == 0) {
        bi = bih[(c * LL + 0) * GG + g];
        const float* wr = Wih0 + (c * GG + g) * (EE + 1);
        for (int e = 0; e <= EE; e++) {
            float bb = b_h2e[c * (EE + 1) + e];
            if (c > 0) bb += b_ad[(c - 1) * (EE + 1) + e];
            bi += wr[e] * bb;
        }
        pv = Wih0[(c * GG + g) * (EE + 1) + EE];
    } else {
        bi = bih[(c * LL + l) * GG + g];
        pv = 0.f;
    }
    bh = bhh[(c * LL + l) * GG + g];
    g_bpk[idx * 4 + 0] = bi;
    g_bpk[idx * 4 + 1] = bh;
    g_bpk[idx * 4 + 2] = pv;
    g_bpk[idx * 4 + 3] = 0.f;
}

// ---------------- pipelined RNN kernel: 2 batches / CTA, 3 layer groups x 96 gates ----------------
__global__ void __launch_bounds__(288, 1) rnn_kernel(const int* __restrict__ x) {
    extern __shared__ __align__(16) char smem_raw[];
    SmemT* sm = reinterpret_cast<SmemT*>(smem_raw);

    const int b0 = blockIdx.x * 2;
    const int tid = threadIdx.x;
    const int l = tid / 96;          // layer group (warp-uniform)
    const int g = tid % 96;          // gate within group
    const bool cellp = (g < HH);     // cell threads: warps 0,3,6

    for (int c = 0; c < CC; c++) {
        // per-thread packed weights (f32x2 pairs)
        const ulonglong2* wv =
            reinterpret_cast<const ulonglong2*>(g_wpk + ((size_t)(c * 288 + tid)) * 96);
        ulonglong2 wi[8], wh[8], wq[8];
#pragma unroll
        for (int i = 0; i < 8; i++) wi[i] = wv[i];
#pragma unroll
        for (int i = 0; i < 8; i++) wh[i] = wv[8 + i];
#pragma unroll
        for (int i = 0; i < 8; i++) wq[i] = wv[16 + i];
        const float4 bias = reinterpret_cast<const float4*>(g_bpk)[c * 288 + tid];

        const float* giC = g_giemb + (size_t)c * VV * GG;
        const float* poutB[2];
        float* hidB[2];
        const int* xc[2];
#pragma unroll
        for (int nb = 0; nb < 2; nb++) {
            poutB[nb] = g_hid + (size_t)((b0 + nb) * CC + (c > 0 ? c - 1 : 0)) * (RR * CL * HH);
            hidB[nb] = g_hid + (size_t)((b0 + nb) * CC + c) * (RR * CL * HH);
            xc[nb] = x + (size_t)((b0 + nb) * CC + c) * (RR * CL);
        }

        // zero prev-row buffers (row 0 reads zeros)
        for (int i = tid; i < 2 * CL * HH; i += 288) (&sm->row[0][0][0])[i] = 0.f;

        // prefetch row 0 (pout + idx) into buffer 0
        if (c > 0) {
            for (int i = tid; i < 1024; i += 288) {
                int nb = i >> 9, j = i & 511;
                cpa16((char*)&sm->pout[nb][0][0][0] + j * 16, (const char*)poutB[nb] + j * 16);
            }
        }
        if (tid < 32) {
            int nb = tid >> 4, j = tid & 15;
            cpa16((char*)&sm->idx[nb][0][0] + j * 16, (const char*)xc[nb] + j * 16);
        }
        asm volatile("cp.async.commit_group;" ::: "memory");

        for (int r = 0; r < RR; r++) {
            const int rb = r & 1, wb = rb ^ 1;
            if (cellp) { sm->h[0][l][g] = 0.f; sm->h[1][l][g] = 0.f; }

            // prefetch row r+1 into buffer wb
            if (r + 1 < RR) {
                if (c > 0) {
                    for (int i = tid; i < 1024; i += 288) {
                        int nb = i >> 9, j = i & 511;
                        cpa16((char*)&sm->pout[nb][wb][0][0] + j * 16,
                              (const char*)(poutB[nb] + (size_t)(r + 1) * CL * HH) + j * 16);
                    }
                }
                if (tid < 32) {
                    int nb = tid >> 4, j = tid & 15;
                    cpa16((char*)&sm->idx[nb][wb][0] + j * 16,
                          (const char*)(xc[nb] + (r + 1) * CL) + j * 16);
                }
            }
            asm volatile("cp.async.commit_group;" ::: "memory");
            asm volatile("cp.async.wait_group 1;" ::: "memory");
            __syncthreads();  // row r data + h reset visible

            const float pos = (float)r * (1.f / 32.f) - 1.f;
            const float bi0 = bias.x + bias.z * pos;
            float gie[2] = {0.f, 0.f};
            if (l == 0) {
                gie[0] = giC[sm->idx[0][rb][0] * GG + g];
                gie[1] = giC[sm->idx[1][rb][0] * GG + g];
            }
            float ho[2] = {0.f, 0.f};

            for (int s = 0; s < CL + LL - 1; s++) {
                const int t = s - l;  // warp-uniform
                const bool act = ((unsigned)t < (unsigned)CL);
                if (act) {
#pragma unroll
                    for (int nb = 0; nb < 2; nb++) {
                        u64 A0 = 0, A1 = 0, B0 = 0, B1 = 0;
                        const ulonglong2* hv =
                            reinterpret_cast<const ulonglong2*>(&sm->h[nb][l][0]);
#pragma unroll
                        for (int i = 0; i < 8; i++) {
                            FMA2(A0, wh[i].x, hv[i].x);
                            FMA2(A1, wh[i].y, hv[i].y);
                        }
                        const ulonglong2* iv =
                            (l == 0) ? reinterpret_cast<const ulonglong2*>(&sm->row[nb][t][0])
                                     : reinterpret_cast<const ulonglong2*>(&sm->h[nb][l - 1][0]);
#pragma unroll
                        for (int i = 0; i < 8; i++) {
                            FMA2(B0, wi[i].x, iv[i].x);
                            FMA2(B1, wi[i].y, iv[i].y);
                        }
                        float a;
                        if (l == 0) {
                            if (c > 0) {
                                const ulonglong2* pv =
                                    reinterpret_cast<const ulonglong2*>(&sm->pout[nb][rb][t][0]);
#pragma unroll
                                for (int i = 0; i < 8; i++) {
                                    FMA2(B0, wq[i].x, pv[i].x);
                                    FMA2(B1, wq[i].y, pv[i].y);
                                }
                            }
                            a = sum2(B0) + sum2(B1) + bi0 + gie[nb];
                        } else {
                            a = sum2(B0) + sum2(B1) + bias.x;
                        }
                        float bsum = sum2(A0) + sum2(A1) + bias.y;
                        if (g < 64) {
                            // r,z gates: finish the sigmoid here (6 warps of overlap hide it)
                            sm->rz[nb][l][g] = sigm_a(a + bsum);
                        } else {
                            sm->n2[nb][l][g - 64] = make_float2(a, bsum);
                        }
                    }
                }
                // prefetch next column's giemb gathers (group 0)
                if (l == 0 && s + 1 < CL) {
                    gie[0] = giC[sm->idx[0][rb][s + 1] * GG + g];
                    gie[1] = giC[sm->idx[1][rb][s + 1] * GG + g];
                }
                __syncthreads();

                if (cellp && act) {  // GRU cell: gates pre-activated; short chain
#pragma unroll
                    for (int nb = 0; nb < 2; nb++) {
                        float rg = sm->rz[nb][l][g];
                        float zg = sm->rz[nb][l][32 + g];
                        float2 nn = sm->n2[nb][l][g];
                        float ng = tanh_f(fmaf(rg, nn.y, nn.x));
                        float hn = fmaf(zg, ho[nb] - ng, ng);
                        ho[nb] = hn;
                        sm->h[nb][l][g] = hn;
                        if (l == 2) {
                            sm->row[nb][t][g] = hn;                       // feeds next row
                            hidB[nb][((size_t)r * CL + t) * HH + g] = hn;  // feeds pout + projection
                        }
                    }
                }
                __syncthreads();
            }
        }
        __syncthreads();
    }
}

// ---------------- output projection with packed f32x2 FMA ----------------
__global__ void __launch_bounds__(256, 2) proj_kernel(const float* __restrict__ Wout,
                                                      const float* __restrict__ bout,
                                                      float* __restrict__ out) {
    __shared__ float Ws[32][264];  // Ws[k][v]
    __shared__ float hs[32][72];   // hs[k][p]
    __shared__ float bs[264];

    const int tid = threadIdx.x;
    const size_t p0 = (size_t)blockIdx.x * 64;

    for (int i = tid; i < VV * HH; i += 256) {
        int v = i >> 5, k = i & 31;
        Ws[k][v] = Wout[i];
    }
    if (tid < 256) bs[tid] = (tid < VV) ? bout[tid] : 0.f;
    if (tid < 2) bs[256 + tid] = bout[256 + tid];
    if (tid < 6) bs[258 + tid] = 0.f;
    {
        const float* hsrc = g_hid + p0 * HH;
        for (int i = tid; i < 64 * HH; i += 256) {
            int p = i >> 5, k = i & 31;
            hs[k][p] = hsrc[i];
        }
    }
    __syncthreads();

    const int tv = tid & 31;
    const int tp = tid >> 5;
    const int vb = tv * 8, pb = tp * 8;

    u64 acc[8][4];
#pragma unroll
    for (int pi = 0; pi < 8; pi++)
#pragma unroll
        for (int j = 0; j < 4; j++) acc[pi][j] = 0ull;

#pragma unroll 2
    for (int k = 0; k < 32; k++) {
        ulonglong2 w0 = *reinterpret_cast<const ulonglong2*>(&Ws[k][vb]);
        ulonglong2 w1 = *reinterpret_cast<const ulonglong2*>(&Ws[k][vb + 4]);
        float4 ha = *reinterpret_cast<const float4*>(&hs[k][pb]);
        float4 hb = *reinterpret_cast<const float4*>(&hs[k][pb + 4]);
        float hv[8] = {ha.x, ha.y, ha.z, ha.w, hb.x, hb.y, hb.z, hb.w};
#pragma unroll
        for (int pi = 0; pi < 8; pi++) {
            u64 hp;
            asm("mov.b64 %0, {%1, %1};" : "=l"(hp) : "f"(hv[pi]));
            FMA2(acc[pi][0], hp, w0.x);
            FMA2(acc[pi][1], hp, w0.y);
            FMA2(acc[pi][2], hp, w1.x);
            FMA2(acc[pi][3], hp, w1.y);
        }
    }

    ulonglong2 bz0 = *reinterpret_cast<const ulonglong2*>(&bs[vb]);
    ulonglong2 bz1 = *reinterpret_cast<const ulonglong2*>(&bs[vb + 4]);
    u64 bzv[4] = {bz0.x, bz0.y, bz1.x, bz1.y};

#pragma unroll
    for (int pi = 0; pi < 8; pi++) {
        size_t base = (p0 + pb + pi) * VV + vb;
#pragma unroll
        for (int j = 0; j < 4; j++) {
            u64 o;
            asm("add.rn.f32x2 %0, %1, %2;" : "=l"(o) : "l"(acc[pi][j]), "l"(bzv[j]));
            *reinterpret_cast<u64*>(&out[base + 2 * j]) = o;
        }
    }

    // tail columns v = 256, 257
    if (tid < 128) {
        int p = tid >> 1;
        int v = 256 + (tid & 1);
        float a = bs[v];
#pragma unroll
        for (int k = 0; k < 32; k++) a = fmaf(hs[k][p], Ws[k][v], a);
        out[(p0 + p) * VV + v] = a;
    }
}

// ---------------- launcher ----------------
extern "C" void kernel_launch(void* const* d_in, const int* in_sizes, int n_in,
                              void* d_out, int out_size) {
    const int* x = (const int*)d_in[0];
    const float* embed = (const float*)d_in[1];
    const float* Wih0 = (const float*)d_in[2];
    const float* Wih_rest = (const float*)d_in[3];
    const float* Whh = (const float*)d_in[4];
    const float* bih = (const float*)d_in[5];
    const float* bhh = (const float*)d_in[6];
    const float* W_h2e = (const float*)d_in[7];
    const float* b_h2e = (const float*)d_in[8];
    const float* W_ad = (const float*)d_in[9];
    const float* b_ad = (const float*)d_in[10];
    const float* W_out = (const float*)d_in[11];
    const float* b_out = (const float*)d_in[12];
    float* out = (float*)d_out;

    cudaFuncSetAttribute(rnn_kernel, cudaFuncAttributeMaxDynamicSharedMemorySize,
                         (int)sizeof(SmemT));

    prep_giemb<<<(CC * VV * GG + 127) / 128, 128>>>(Wih0, embed);
    prep_wpk2<<<(CC * 288 * 96 + 127) / 128, 128>>>(Wih0, Wih_rest, Whh, W_h2e, W_ad);
    prep_bpk2<<<(CC * 288 + 127) / 128, 128>>>(Wih0, bih, bhh, b_h2e, b_ad);
    rnn_kernel<<<BB / 2, 288, sizeof(SmemT)>>>(x);
    proj_kernel<<<(BB * CC * RR * CL) / 64, 256>>>(W_out, b_out, out);
}

// round 7
// speedup vs baseline: 1.6811x; 1.6811x over previous
#include <cuda_runtime.h>

#define BB 64
#define CC 3
#define RR 64
#define CL 64
#define EE 64
#define HH 32
#define LL 3
#define VV 258
#define GG 96   // 3*H

typedef unsigned long long u64;

// ---------------- scratch (device globals; no allocation) ----------------
__device__ float g_giemb[CC * VV * GG];                   // [c][v][g] = Wih0[:, :64] @ embed
__device__ float g_wpk[CC * 288 * 96];                    // per-thread packed rows: wi[32], wh[32], wq[32]
__device__ float g_bpk[CC * 288 * 4];                     // per-thread bias: (bi, bh, pv, 0)
__device__ float g_hid[(size_t)BB * CC * RR * CL * HH];   // all hidden outputs (~100 MB)
__device__ float g_qpre[(size_t)CC * BB * RR * CL * GG];  // hoisted gi0 input terms (~302 MB)

// ---------------- helpers ----------------
#define FMA2(acc, a, b) asm("fma.rn.f32x2 %0, %1, %2, %0;" : "+l"(acc) : "l"(a), "l"(b))

__device__ __forceinline__ float sum2(u64 a) {
    float lo = __uint_as_float((unsigned)(a & 0xffffffffull));
    float hi = __uint_as_float((unsigned)(a >> 32));
    return lo + hi;
}
// sigmoid via MUFU.TANH (validated exact-enough in R6: rel_err unchanged)
__device__ __forceinline__ float sigm_a(float x) {
    float t;
    asm("tanh.approx.f32 %0, %1;" : "=f"(t) : "f"(0.5f * x));
    return fmaf(0.5f, t, 0.5f);
}
__device__ __forceinline__ float tanh_a(float x) {
    float t;
    asm("tanh.approx.f32 %0, %1;" : "=f"(t) : "f"(x));
    return t;
}

// ---------------- precompute kernels ----------------
__global__ void prep_giemb(const float* __restrict__ Wih0, const float* __restrict__ embed) {
    int idx = blockIdx.x * blockDim.x + threadIdx.x;
    if (idx >= CC * VV * GG) return;
    int c = idx / (VV * GG);
    int rem = idx % (VV * GG);
    int v = rem / GG;
    int g = rem % GG;
    const float* wr = Wih0 + (c * GG + g) * (EE + 1);
    const float* em = embed + (c * VV + v) * EE;
    float acc = 0.f;
#pragma unroll
    for (int e = 0; e < EE; e++) acc += wr[e] * em[e];
    g_giemb[idx] = acc;
}

// Per (c, thread t in [0,288)): l = t/96, g = t%96. 96 floats:
//   [0:32)  wi : l==0 -> Wfh[g]  (Wih0 @ W_h2e); l>=1 -> Wih_rest[c][l-1][g]
//   [32:64) wh : Whh[c][l][g]
//   [64:96) wq : l==0 && c>0 -> Wfad[g] (Wih0 @ W_ad); else 0   (used by qpre kernel)
__global__ void prep_wpk2(const float* __restrict__ Wih0, const float* __restrict__ Wih_rest,
                          const float* __restrict__ Whh, const float* __restrict__ W_h2e,
                          const float* __restrict__ W_ad) {
    int idx = blockIdx.x * blockDim.x + threadIdx.x;
    if (idx >= CC * 288 * 96) return;
    int c = idx / (288 * 96);
    int rem = idx % (288 * 96);
    int t = rem / 96;
    int j = rem % 96;
    int s = j / 32;
    int k = j % 32;
    int l = t / 96;
    int g = t % 96;
    float val = 0.f;
    if (s == 0) {
        if (l == 0) {
            const float* wr = Wih0 + (c * GG + g) * (EE + 1);
            for (int e = 0; e <= EE; e++)
                val += wr[e] * W_h2e[(c * (EE + 1) + e) * HH + k];
        } else {
            val = Wih_rest[((c * (LL - 1) + (l - 1)) * GG + g) * HH + k];
        }
    } else if (s == 1) {
        val = Whh[((c * LL + l) * GG + g) * HH + k];
    } else {
        if (l == 0 && c > 0) {
            const float* wr = Wih0 + (c * GG + g) * (EE + 1);
            for (int e = 0; e <= EE; e++)
                val += wr[e] * W_ad[((c - 1) * (EE + 1) + e) * HH + k];
        }
    }
    g_wpk[idx] = val;
}

__global__ void prep_bpk2(const float* __restrict__ Wih0, const float* __restrict__ bih,
                          const float* __restrict__ bhh, const float* __restrict__ b_h2e,
                          const float* __restrict__ b_ad) {
    int idx = blockIdx.x * blockDim.x + threadIdx.x;
    if (idx >= CC * 288) return;
    int c = idx / 288;
    int t = idx % 288;
    int l = t / 96;
    int g = t % 96;
    float bi, bh, pv;
    if (l == 0) {
        bi = bih[(c * LL + 0) * GG + g];
        const float* wr = Wih0 + (c * GG + g) * (EE + 1);
        for (int e = 0; e <= EE; e++) {
            float bb = b_h2e[c * (EE + 1) + e];
            if (c > 0) bb += b_ad[(c - 1) * (EE + 1) + e];
            bi += wr[e] * bb;
        }
        pv = Wih0[(c * GG + g) * (EE + 1) + EE];
    } else {
        bi = bih[(c * LL + l) * GG + g];
        pv = 0.f;
    }
    bh = bhh[(c * LL + l) * GG + g];
    g_bpk[idx * 4 + 0] = bi;
    g_bpk[idx * 4 + 1] = bh;
    g_bpk[idx * 4 + 2] = pv;
    g_bpk[idx * 4 + 3] = 0.f;
}

// ---------------- qpre: per-channel hoist of gather + channel-adapter GEMM ----------------
// qpre[c][pos][g] = giemb[c][x[pos]][g] + (c>0 ? Wfad[c][g] . hid[c-1][pos] : 0)
// pos = b*4096 + r*64 + t. Runs after rnn(c-1). grid = 8192, block = 96.
__global__ void __launch_bounds__(96, 8) qpre_kernel(int c, const int* __restrict__ x) {
    __shared__ __align__(16) float sh[32][32];
    __shared__ int sx[32];
    const int g = threadIdx.x;
    const size_t pos0 = (size_t)blockIdx.x * 32;
    const int b = (int)(pos0 >> 12);
    const int rt0 = (int)(pos0 & 4095);

    ulonglong2 wq[8];
    if (c > 0) {
        const ulonglong2* wsrc =
            reinterpret_cast<const ulonglong2*>(g_wpk + ((size_t)(c * 288 + g)) * 96 + 64);
#pragma unroll
        for (int i = 0; i < 8; i++) wq[i] = wsrc[i];
        const float4* hsrc = reinterpret_cast<const float4*>(
            g_hid + ((size_t)(b * CC + c - 1) * (RR * CL) + rt0) * HH);
        float4* shd = reinterpret_cast<float4*>(&sh[0][0]);
        for (int i = g; i < 256; i += 96) shd[i] = hsrc[i];
    }
    if (g < 32) sx[g] = x[((size_t)(b * CC + c) * (RR * CL)) + rt0 + g];
    __syncthreads();

    const float* giC = g_giemb + (size_t)c * VV * GG;
    float* outp = g_qpre + ((size_t)c * (BB * RR * CL) + pos0) * GG + g;
#pragma unroll 4
    for (int p = 0; p < 32; p++) {
        float val = __ldg(giC + (size_t)sx[p] * GG + g);
        if (c > 0) {
            u64 A0 = 0, A1 = 0;
            const ulonglong2* hv = reinterpret_cast<const ulonglong2*>(&sh[p][0]);
#pragma unroll
            for (int i = 0; i < 8; i++) {
                FMA2(A0, wq[i].x, hv[i].x);
                FMA2(A1, wq[i].y, hv[i].y);
            }
            val += sum2(A0) + sum2(A1);
        }
        outp[(size_t)p * GG] = val;
    }
}

// ---------------- pipelined RNN kernel (one channel per launch) ----------------
// 288 threads = 3 layer groups x 96 gates. Step s: group l works column t = s - l.
// Layer-0's input-side terms come precomputed in s_qx; l0 threads build next row's
// s_qx during the current row (off the critical path).
__global__ void __launch_bounds__(288, 1) rnn_kernel(int c) {
    const int b = blockIdx.x;
    const int tid = threadIdx.x;
    const int l = tid / 96;          // layer group (warp-uniform)
    const int g = tid % 96;          // gate within group

    __shared__ __align__(16) float s_row[CL][HH];   // current row's layer-2 outputs
    __shared__ float s_qx[CL][GG];                   // layer-0 input-side gate sums
    __shared__ __align__(16) float s_h[LL][HH];      // per-layer hidden
    __shared__ float s_rz[LL][64];                   // finished sigma(r), sigma(z)
    __shared__ __align__(8) float2 s_n2[LL][HH];     // (i_n, h_n)

    // per-thread packed weights (f32x2 pairs): wi = input-side row, wh = hidden-side row
    const ulonglong2* wv =
        reinterpret_cast<const ulonglong2*>(g_wpk + ((size_t)(c * 288 + tid)) * 96);
    ulonglong2 wi[8], wh[8];
#pragma unroll
    for (int i = 0; i < 8; i++) wi[i] = wv[i];
#pragma unroll
    for (int i = 0; i < 8; i++) wh[i] = wv[8 + i];
    const float4 bias = reinterpret_cast<const float4*>(g_bpk)[c * 288 + tid];

    const float* qpreC = g_qpre + ((size_t)c * BB + b) * (RR * CL) * GG;
    float* hidG = g_hid + (size_t)(b * CC + c) * (RR * CL * HH);

    // row-0 prologue: h2_prev = 0, so qx = qpre + bias(pos=-1)
    if (l == 0) {
        const float b00 = bias.x - bias.z;
        for (int t = 0; t < CL; t++) s_qx[t][g] = __ldg(qpreC + (size_t)t * GG + g) + b00;
    }

    for (int r = 0; r < RR; r++) {
        if (g < HH) s_h[l][g] = 0.f;
        float ho = 0.f;
        const float bi0n = bias.x + bias.z * ((float)(r + 1) * (1.f / 32.f) - 1.f);
        const float* qnext = qpreC + (size_t)(r + 1) * CL * GG;
        const bool doBuild = (r < RR - 1);
        float qa = 0.f, qb = 0.f;
        __syncthreads();  // h reset + prologue/qx visible

        for (int s = 0; s < CL + 3; s++) {
            if (l == 0) {
                if (s < CL) {
                    // gh0 = Whh0 . h0
                    u64 A0 = 0, A1 = 0;
                    const ulonglong2* hv = reinterpret_cast<const ulonglong2*>(&s_h[0][0]);
#pragma unroll
                    for (int i = 0; i < 8; i++) {
                        FMA2(A0, wh[i].x, hv[i].x);
                        FMA2(A1, wh[i].y, hv[i].y);
                    }
                    float ah = sum2(A0) + sum2(A1) + bias.y;
                    float ai = s_qx[s][g];
                    if (g < 64) s_rz[0][g] = sigm_a(ai + ah);
                    else s_n2[0][g - 64] = make_float2(ai, ah);
                }
                // next-row qx build (off critical path): qv issued 2 steps ago
                float qv = qa;
                qa = qb;
                if (doBuild) {
                    int ti = s - 1;
                    if ((unsigned)ti < (unsigned)CL) qb = __ldg(qnext + (size_t)ti * GG + g);
                    int tb = s - 3;
                    if ((unsigned)tb < (unsigned)CL) {
                        u64 B0 = 0, B1 = 0;
                        const ulonglong2* rv =
                            reinterpret_cast<const ulonglong2*>(&s_row[tb][0]);
#pragma unroll
                        for (int i = 0; i < 8; i++) {
                            FMA2(B0, wi[i].x, rv[i].x);
                            FMA2(B1, wi[i].y, rv[i].y);
                        }
                        s_qx[tb][g] = sum2(B0) + sum2(B1) + bi0n + qv;
                    }
                }
            } else {
                const int t = s - l;
                if ((unsigned)t < (unsigned)CL) {
                    u64 A0 = 0, A1 = 0, B0 = 0, B1 = 0;
                    const ulonglong2* hv = reinterpret_cast<const ulonglong2*>(&s_h[l][0]);
                    const ulonglong2* iv = reinterpret_cast<const ulonglong2*>(&s_h[l - 1][0]);
#pragma unroll
                    for (int i = 0; i < 8; i++) {
                        FMA2(A0, wh[i].x, hv[i].x);
                        FMA2(A1, wh[i].y, hv[i].y);
                        FMA2(B0, wi[i].x, iv[i].x);
                        FMA2(B1, wi[i].y, iv[i].y);
                    }
                    float ah = sum2(A0) + sum2(A1) + bias.y;
                    float ai = sum2(B0) + sum2(B1) + bias.x;
                    if (g < 64) s_rz[l][g] = sigm_a(ai + ah);
                    else s_n2[l][g - 64] = make_float2(ai, ah);
                }
            }
            __syncthreads();

            if (g < HH) {
                const int t = s - l;
                if ((unsigned)t < (unsigned)CL) {
                    float rg = s_rz[l][g];
                    float zg = s_rz[l][32 + g];
                    float2 nn = s_n2[l][g];
                    float ng = tanh_a(fmaf(rg, nn.y, nn.x));
                    float hn = fmaf(zg, ho - ng, ng);
                    ho = hn;
                    s_h[l][g] = hn;
                    if (l == 2) {
                        s_row[t][g] = hn;                          // feeds next row's qx build
                        hidG[((size_t)r * CL + t) * HH + g] = hn;  // feeds qpre(c+1) + projection
                    }
                }
            }
            __syncthreads();
        }
    }
}

// ---------------- output projection with packed f32x2 FMA ----------------
__global__ void __launch_bounds__(256, 2) proj_kernel(const float* __restrict__ Wout,
                                                      const float* __restrict__ bout,
                                                      float* __restrict__ out) {
    __shared__ float Ws[32][264];  // Ws[k][v]
    __shared__ float hs[32][72];   // hs[k][p]
    __shared__ float bs[264];

    const int tid = threadIdx.x;
    const size_t p0 = (size_t)blockIdx.x * 64;

    for (int i = tid; i < VV * HH; i += 256) {
        int v = i >> 5, k = i & 31;
        Ws[k][v] = Wout[i];
    }
    if (tid < 256) bs[tid] = (tid < VV) ? bout[tid] : 0.f;
    if (tid < 2) bs[256 + tid] = bout[256 + tid];
    if (tid < 6) bs[258 + tid] = 0.f;
    {
        const float* hsrc = g_hid + p0 * HH;
        for (int i = tid; i < 64 * HH; i += 256) {
            int p = i >> 5, k = i & 31;
            hs[k][p] = hsrc[i];
        }
    }
    __syncthreads();

    const int tv = tid & 31;
    const int tp = tid >> 5;
    const int vb = tv * 8, pb = tp * 8;

    u64 acc[8][4];
#pragma unroll
    for (int pi = 0; pi < 8; pi++)
#pragma unroll
        for (int j = 0; j < 4; j++) acc[pi][j] = 0ull;

#pragma unroll 2
    for (int k = 0; k < 32; k++) {
        ulonglong2 w0 = *reinterpret_cast<const ulonglong2*>(&Ws[k][vb]);
        ulonglong2 w1 = *reinterpret_cast<const ulonglong2*>(&Ws[k][vb + 4]);
        float4 ha = *reinterpret_cast<const float4*>(&hs[k][pb]);
        float4 hb = *reinterpret_cast<const float4*>(&hs[k][pb + 4]);
        float hv[8] = {ha.x, ha.y, ha.z, ha.w, hb.x, hb.y, hb.z, hb.w};
#pragma unroll
        for (int pi = 0; pi < 8; pi++) {
            u64 hp;
            asm("mov.b64 %0, {%1, %1};" : "=l"(hp) : "f"(hv[pi]));
            FMA2(acc[pi][0], hp, w0.x);
            FMA2(acc[pi][1], hp, w0.y);
            FMA2(acc[pi][2], hp, w1.x);
            FMA2(acc[pi][3], hp, w1.y);
        }
    }

    ulonglong2 bz0 = *reinterpret_cast<const ulonglong2*>(&bs[vb]);
    ulonglong2 bz1 = *reinterpret_cast<const ulonglong2*>(&bs[vb + 4]);
    u64 bzv[4] = {bz0.x, bz0.y, bz1.x, bz1.y};

#pragma unroll
    for (int pi = 0; pi < 8; pi++) {
        size_t base = (p0 + pb + pi) * VV + vb;
#pragma unroll
        for (int j = 0; j < 4; j++) {
            u64 o;
            asm("add.rn.f32x2 %0, %1, %2;" : "=l"(o) : "l"(acc[pi][j]), "l"(bzv[j]));
            *reinterpret_cast<u64*>(&out[base + 2 * j]) = o;
        }
    }

    // tail columns v = 256, 257
    if (tid < 128) {
        int p = tid >> 1;
        int v = 256 + (tid & 1);
        float a = bs[v];
#pragma unroll
        for (int k = 0; k < 32; k++) a = fmaf(hs[k][p], Ws[k][v], a);
        out[(p0 + p) * VV + v] = a;
    }
}

// ---------------- launcher ----------------
extern "C" void kernel_launch(void* const* d_in, const int* in_sizes, int n_in,
                              void* d_out, int out_size) {
    const int* x = (const int*)d_in[0];
    const float* embed = (const float*)d_in[1];
    const float* Wih0 = (const float*)d_in[2];
    const float* Wih_rest = (const float*)d_in[3];
    const float* Whh = (const float*)d_in[4];
    const float* bih = (const float*)d_in[5];
    const float* bhh = (const float*)d_in[6];
    const float* W_h2e = (const float*)d_in[7];
    const float* b_h2e = (const float*)d_in[8];
    const float* W_ad = (const float*)d_in[9];
    const float* b_ad = (const float*)d_in[10];
    const float* W_out = (const float*)d_in[11];
    const float* b_out = (const float*)d_in[12];
    float* out = (float*)d_out;

    prep_giemb<<<(CC * VV * GG + 127) / 128, 128>>>(Wih0, embed);
    prep_wpk2<<<(CC * 288 * 96 + 127) / 128, 128>>>(Wih0, Wih_rest, Whh, W_h2e, W_ad);
    prep_bpk2<<<(CC * 288 + 127) / 128, 128>>>(Wih0, bih, bhh, b_h2e, b_ad);

    for (int c = 0; c < CC; c++) {
        qpre_kernel<<<(BB * RR * CL) / 32, 96>>>(c, x);
        rnn_kernel<<<BB, 288>>>(c);
    }
    proj_kernel<<<(BB * CC * RR * CL) / 64, 256>>>(W_out, b_out, out);
}

// round 8
// speedup vs baseline: 1.6824x; 1.0008x over previous
#include <cuda_runtime.h>

#define BB 64
#define CC 3
#define RR 64
#define CL 64
#define EE 64
#define HH 32
#define LL 3
#define VV 258
#define GG 96   // 3*H

typedef unsigned long long u64;

// ---------------- scratch (device globals; no allocation) ----------------
__device__ float g_giemb[CC * VV * GG];                   // [c][v][g] = Wih0[:, :64] @ embed
__device__ float g_wpk[CC * 288 * 96];                    // per-thread packed rows: wi[32], wh[32], wq[32]
__device__ float g_bpk[CC * 288 * 4];                     // per-thread bias: (bi, bh, pv, 0)
__device__ float g_hid[(size_t)BB * CC * RR * CL * HH];   // all hidden outputs (~100 MB)
__device__ float g_qpre[(size_t)CC * BB * RR * CL * GG];  // hoisted gi0 input terms (~302 MB)

// ---------------- helpers ----------------
#define FMA2(acc, a, b) asm("fma.rn.f32x2 %0, %1, %2, %0;" : "+l"(acc) : "l"(a), "l"(b))

__device__ __forceinline__ float sum2(u64 a) {
    float lo = __uint_as_float((unsigned)(a & 0xffffffffull));
    float hi = __uint_as_float((unsigned)(a >> 32));
    return lo + hi;
}
// sigmoid via MUFU.TANH (validated exact-enough in R6: rel_err unchanged)
__device__ __forceinline__ float sigm_a(float x) {
    float t;
    asm("tanh.approx.f32 %0, %1;" : "=f"(t) : "f"(0.5f * x));
    return fmaf(0.5f, t, 0.5f);
}
__device__ __forceinline__ float tanh_a(float x) {
    float t;
    asm("tanh.approx.f32 %0, %1;" : "=f"(t) : "f"(x));
    return t;
}

// ---------------- precompute kernels ----------------
__global__ void prep_giemb(const float* __restrict__ Wih0, const float* __restrict__ embed) {
    int idx = blockIdx.x * blockDim.x + threadIdx.x;
    if (idx >= CC * VV * GG) return;
    int c = idx / (VV * GG);
    int rem = idx % (VV * GG);
    int v = rem / GG;
    int g = rem % GG;
    const float* wr = Wih0 + (c * GG + g) * (EE + 1);
    const float* em = embed + (c * VV + v) * EE;
    float acc = 0.f;
#pragma unroll
    for (int e = 0; e < EE; e++) acc += wr[e] * em[e];
    g_giemb[idx] = acc;
}

// Per (c, thread t in [0,288)): l = t/96, g = t%96. 96 floats:
//   [0:32)  wi : l==0 -> Wfh[g]  (Wih0 @ W_h2e); l>=1 -> Wih_rest[c][l-1][g]
//   [32:64) wh : Whh[c][l][g]
//   [64:96) wq : l==0 && c>0 -> Wfad[g] (Wih0 @ W_ad); else 0   (used by qpre kernel)
__global__ void prep_wpk2(const float* __restrict__ Wih0, const float* __restrict__ Wih_rest,
                          const float* __restrict__ Whh, const float* __restrict__ W_h2e,
                          const float* __restrict__ W_ad) {
    int idx = blockIdx.x * blockDim.x + threadIdx.x;
    if (idx >= CC * 288 * 96) return;
    int c = idx / (288 * 96);
    int rem = idx % (288 * 96);
    int t = rem / 96;
    int j = rem % 96;
    int s = j / 32;
    int k = j % 32;
    int l = t / 96;
    int g = t % 96;
    float val = 0.f;
    if (s == 0) {
        if (l == 0) {
            const float* wr = Wih0 + (c * GG + g) * (EE + 1);
            for (int e = 0; e <= EE; e++)
                val += wr[e] * W_h2e[(c * (EE + 1) + e) * HH + k];
        } else {
            val = Wih_rest[((c * (LL - 1) + (l - 1)) * GG + g) * HH + k];
        }
    } else if (s == 1) {
        val = Whh[((c * LL + l) * GG + g) * HH + k];
    } else {
        if (l == 0 && c > 0) {
            const float* wr = Wih0 + (c * GG + g) * (EE + 1);
            for (int e = 0; e <= EE; e++)
                val += wr[e] * W_ad[((c - 1) * (EE + 1) + e) * HH + k];
        }
    }
    g_wpk[idx] = val;
}

__global__ void prep_bpk2(const float* __restrict__ Wih0, const float* __restrict__ bih,
                          const float* __restrict__ bhh, const float* __restrict__ b_h2e,
                          const float* __restrict__ b_ad) {
    int idx = blockIdx.x * blockDim.x + threadIdx.x;
    if (idx >= CC * 288) return;
    int c = idx / 288;
    int t = idx % 288;
    int l = t / 96;
    int g = t % 96;
    float bi, bh, pv;
    if (l == 0) {
        bi = bih[(c * LL + 0) * GG + g];
        const float* wr = Wih0 + (c * GG + g) * (EE + 1);
        for (int e = 0; e <= EE; e++) {
            float bb = b_h2e[c * (EE + 1) + e];
            if (c > 0) bb += b_ad[(c - 1) * (EE + 1) + e];
            bi += wr[e] * bb;
        }
        pv = Wih0[(c * GG + g) * (EE + 1) + EE];
    } else {
        bi = bih[(c * LL + l) * GG + g];
        pv = 0.f;
    }
    bh = bhh[(c * LL + l) * GG + g];
    g_bpk[idx * 4 + 0] = bi;
    g_bpk[idx * 4 + 1] = bh;
    g_bpk[idx * 4 + 2] = pv;
    g_bpk[idx * 4 + 3] = 0.f;
}

// ---------------- qpre: per-channel hoist of gather + channel-adapter GEMM ----------------
// qpre[c][pos][g] = giemb[c][x[pos]][g] + (c>0 ? Wfad[c][g] . hid[c-1][pos] : 0)
// pos = b*4096 + r*64 + t. Runs after rnn(c-1). grid = 8192, block = 96.
__global__ void __launch_bounds__(96, 8) qpre_kernel(int c, const int* __restrict__ x) {
    __shared__ __align__(16) float sh[32][32];
    __shared__ int sx[32];
    const int g = threadIdx.x;
    const size_t pos0 = (size_t)blockIdx.x * 32;
    const int b = (int)(pos0 >> 12);
    const int rt0 = (int)(pos0 & 4095);

    ulonglong2 wq[8];
    if (c > 0) {
        const ulonglong2* wsrc =
            reinterpret_cast<const ulonglong2*>(g_wpk + ((size_t)(c * 288 + g)) * 96 + 64);
#pragma unroll
        for (int i = 0; i < 8; i++) wq[i] = wsrc[i];
        const float4* hsrc = reinterpret_cast<const float4*>(
            g_hid + ((size_t)(b * CC + c - 1) * (RR * CL) + rt0) * HH);
        float4* shd = reinterpret_cast<float4*>(&sh[0][0]);
        for (int i = g; i < 256; i += 96) shd[i] = hsrc[i];
    }
    if (g < 32) sx[g] = x[((size_t)(b * CC + c) * (RR * CL)) + rt0 + g];
    __syncthreads();

    const float* giC = g_giemb + (size_t)c * VV * GG;
    float* outp = g_qpre + ((size_t)c * (BB * RR * CL) + pos0) * GG + g;
#pragma unroll 4
    for (int p = 0; p < 32; p++) {
        float val = __ldg(giC + (size_t)sx[p] * GG + g);
        if (c > 0) {
            u64 A0 = 0, A1 = 0;
            const ulonglong2* hv = reinterpret_cast<const ulonglong2*>(&sh[p][0]);
#pragma unroll
            for (int i = 0; i < 8; i++) {
                FMA2(A0, wq[i].x, hv[i].x);
                FMA2(A1, wq[i].y, hv[i].y);
            }
            val += sum2(A0) + sum2(A1);
        }
        outp[(size_t)p * GG] = val;
    }
}

// ---------------- pipelined RNN kernel (one channel per launch) ----------------
// 288 threads = 3 layer groups x 96 gates. Step s: group l works column t = s - l.
// Layer-0's input-side terms come precomputed in s_qx; l0 threads build next row's
// s_qx during the current row (off the critical path).
__global__ void __launch_bounds__(288, 1) rnn_kernel(int c) {
    const int b = blockIdx.x;
    const int tid = threadIdx.x;
    const int l = tid / 96;          // layer group (warp-uniform)
    const int g = tid % 96;          // gate within group

    __shared__ __align__(16) float s_row[CL][HH];   // current row's layer-2 outputs
    __shared__ float s_qx[CL][GG];                   // layer-0 input-side gate sums
    __shared__ __align__(16) float s_h[LL][HH];      // per-layer hidden
    __shared__ float s_rz[LL][64];                   // finished sigma(r), sigma(z)
    __shared__ __align__(8) float2 s_n2[LL][HH];     // (i_n, h_n)

    // per-thread packed weights (f32x2 pairs): wi = input-side row, wh = hidden-side row
    const ulonglong2* wv =
        reinterpret_cast<const ulonglong2*>(g_wpk + ((size_t)(c * 288 + tid)) * 96);
    ulonglong2 wi[8], wh[8];
#pragma unroll
    for (int i = 0; i < 8; i++) wi[i] = wv[i];
#pragma unroll
    for (int i = 0; i < 8; i++) wh[i] = wv[8 + i];
    const float4 bias = reinterpret_cast<const float4*>(g_bpk)[c * 288 + tid];

    const float* qpreC = g_qpre + ((size_t)c * BB + b) * (RR * CL) * GG;
    float* hidG = g_hid + (size_t)(b * CC + c) * (RR * CL * HH);

    // row-0 prologue: h2_prev = 0, so qx = qpre + bias(pos=-1)
    if (l == 0) {
        const float b00 = bias.x - bias.z;
        for (int t = 0; t < CL; t++) s_qx[t][g] = __ldg(qpreC + (size_t)t * GG + g) + b00;
    }

    for (int r = 0; r < RR; r++) {
        if (g < HH) s_h[l][g] = 0.f;
        float ho = 0.f;
        const float bi0n = bias.x + bias.z * ((float)(r + 1) * (1.f / 32.f) - 1.f);
        const float* qnext = qpreC + (size_t)(r + 1) * CL * GG;
        const bool doBuild = (r < RR - 1);
        float qa = 0.f, qb = 0.f;
        __syncthreads();  // h reset + prologue/qx visible

        for (int s = 0; s < CL + 3; s++) {
            if (l == 0) {
                if (s < CL) {
                    // gh0 = Whh0 . h0
                    u64 A0 = 0, A1 = 0;
                    const ulonglong2* hv = reinterpret_cast<const ulonglong2*>(&s_h[0][0]);
#pragma unroll
                    for (int i = 0; i < 8; i++) {
                        FMA2(A0, wh[i].x, hv[i].x);
                        FMA2(A1, wh[i].y, hv[i].y);
                    }
                    float ah = sum2(A0) + sum2(A1) + bias.y;
                    float ai = s_qx[s][g];
                    if (g < 64) s_rz[0][g] = sigm_a(ai + ah);
                    else s_n2[0][g - 64] = make_float2(ai, ah);
                }
                // next-row qx build (off critical path): qv issued 2 steps ago
                float qv = qa;
                qa = qb;
                if (doBuild) {
                    int ti = s - 1;
                    if ((unsigned)ti < (unsigned)CL) qb = __ldg(qnext + (size_t)ti * GG + g);
                    int tb = s - 3;
                    if ((unsigned)tb < (unsigned)CL) {
                        u64 B0 = 0, B1 = 0;
                        const ulonglong2* rv =
                            reinterpret_cast<const ulonglong2*>(&s_row[tb][0]);
#pragma unroll
                        for (int i = 0; i < 8; i++) {
                            FMA2(B0, wi[i].x, rv[i].x);
                            FMA2(B1, wi[i].y, rv[i].y);
                        }
                        s_qx[tb][g] = sum2(B0) + sum2(B1) + bi0n + qv;
                    }
                }
            } else {
                const int t = s - l;
                if ((unsigned)t < (unsigned)CL) {
                    u64 A0 = 0, A1 = 0, B0 = 0, B1 = 0;
                    const ulonglong2* hv = reinterpret_cast<const ulonglong2*>(&s_h[l][0]);
                    const ulonglong2* iv = reinterpret_cast<const ulonglong2*>(&s_h[l - 1][0]);
#pragma unroll
                    for (int i = 0; i < 8; i++) {
                        FMA2(A0, wh[i].x, hv[i].x);
                        FMA2(A1, wh[i].y, hv[i].y);
                        FMA2(B0, wi[i].x, iv[i].x);
                        FMA2(B1, wi[i].y, iv[i].y);
                    }
                    float ah = sum2(A0) + sum2(A1) + bias.y;
                    float ai = sum2(B0) + sum2(B1) + bias.x;
                    if (g < 64) s_rz[l][g] = sigm_a(ai + ah);
                    else s_n2[l][g - 64] = make_float2(ai, ah);
                }
            }
            __syncthreads();

            if (g < HH) {
                const int t = s - l;
                if ((unsigned)t < (unsigned)CL) {
                    float rg = s_rz[l][g];
                    float zg = s_rz[l][32 + g];
                    float2 nn = s_n2[l][g];
                    float ng = tanh_a(fmaf(rg, nn.y, nn.x));
                    float hn = fmaf(zg, ho - ng, ng);
                    ho = hn;
                    s_h[l][g] = hn;
                    if (l == 2) {
                        s_row[t][g] = hn;                          // feeds next row's qx build
                        hidG[((size_t)r * CL + t) * HH + g] = hn;  // feeds qpre(c+1) + projection
                    }
                }
            }
            __syncthreads();
        }
    }
}

// ---------------- output projection with packed f32x2 FMA ----------------
__global__ void __launch_bounds__(256, 2) proj_kernel(const float* __restrict__ Wout,
                                                      const float* __restrict__ bout,
                                                      float* __restrict__ out) {
    __shared__ float Ws[32][264];  // Ws[k][v]
    __shared__ float hs[32][72];   // hs[k][p]
    __shared__ float bs[264];

    const int tid = threadIdx.x;
    const size_t p0 = (size_t)blockIdx.x * 64;

    for (int i = tid; i < VV * HH; i += 256) {
        int v = i >> 5, k = i & 31;
        Ws[k][v] = Wout[i];
    }
    if (tid < 256) bs[tid] = (tid < VV) ? bout[tid] : 0.f;
    if (tid < 2) bs[256 + tid] = bout[256 + tid];
    if (tid < 6) bs[258 + tid] = 0.f;
    {
        const float* hsrc = g_hid + p0 * HH;
        for (int i = tid; i < 64 * HH; i += 256) {
            int p = i >> 5, k = i & 31;
            hs[k][p] = hsrc[i];
        }
    }
    __syncthreads();

    const int tv = tid & 31;
    const int tp = tid >> 5;
    const int vb = tv * 8, pb = tp * 8;

    u64 acc[8][4];
#pragma unroll
    for (int pi = 0; pi < 8; pi++)
#pragma unroll
        for (int j = 0; j < 4; j++) acc[pi][j] = 0ull;

#pragma unroll 2
    for (int k = 0; k < 32; k++) {
        ulonglong2 w0 = *reinterpret_cast<const ulonglong2*>(&Ws[k][vb]);
        ulonglong2 w1 = *reinterpret_cast<const ulonglong2*>(&Ws[k][vb + 4]);
        float4 ha = *reinterpret_cast<const float4*>(&hs[k][pb]);
        float4 hb = *reinterpret_cast<const float4*>(&hs[k][pb + 4]);
        float hv[8] = {ha.x, ha.y, ha.z, ha.w, hb.x, hb.y, hb.z, hb.w};
#pragma unroll
        for (int pi = 0; pi < 8; pi++) {
            u64 hp;
            asm("mov.b64 %0, {%1, %1};" : "=l"(hp) : "f"(hv[pi]));
            FMA2(acc[pi][0], hp, w0.x);
            FMA2(acc[pi][1], hp, w0.y);
            FMA2(acc[pi][2], hp, w1.x);
            FMA2(acc[pi][3], hp, w1.y);
        }
    }

    ulonglong2 bz0 = *reinterpret_cast<const ulonglong2*>(&bs[vb]);
    ulonglong2 bz1 = *reinterpret_cast<const ulonglong2*>(&bs[vb + 4]);
    u64 bzv[4] = {bz0.x, bz0.y, bz1.x, bz1.y};

#pragma unroll
    for (int pi = 0; pi < 8; pi++) {
        size_t base = (p0 + pb + pi) * VV + vb;
#pragma unroll
        for (int j = 0; j < 4; j++) {
            u64 o;
            asm("add.rn.f32x2 %0, %1, %2;" : "=l"(o) : "l"(acc[pi][j]), "l"(bzv[j]));
            *reinterpret_cast<u64*>(&out[base + 2 * j]) = o;
        }
    }

    // tail columns v = 256, 257
    if (tid < 128) {
        int p = tid >> 1;
        int v = 256 + (tid & 1);
        float a = bs[v];
#pragma unroll
        for (int k = 0; k < 32; k++) a = fmaf(hs[k][p], Ws[k][v], a);
        out[(p0 + p) * VV + v] = a;
    }
}

// ---------------- launcher ----------------
extern "C" void kernel_launch(void* const* d_in, const int* in_sizes, int n_in,
                              void* d_out, int out_size) {
    const int* x = (const int*)d_in[0];
    const float* embed = (const float*)d_in[1];
    const float* Wih0 = (const float*)d_in[2];
    const float* Wih_rest = (const float*)d_in[3];
    const float* Whh = (const float*)d_in[4];
    const float* bih = (const float*)d_in[5];
    const float* bhh = (const float*)d_in[6];
    const float* W_h2e = (const float*)d_in[7];
    const float* b_h2e = (const float*)d_in[8];
    const float* W_ad = (const float*)d_in[9];
    const float* b_ad = (const float*)d_in[10];
    const float* W_out = (const float*)d_in[11];
    const float* b_out = (const float*)d_in[12];
    float* out = (float*)d_out;

    prep_giemb<<<(CC * VV * GG + 127) / 128, 128>>>(Wih0, embed);
    prep_wpk2<<<(CC * 288 * 96 + 127) / 128, 128>>>(Wih0, Wih_rest, Whh, W_h2e, W_ad);
    prep_bpk2<<<(CC * 288 + 127) / 128, 128>>>(Wih0, bih, bhh, b_h2e, b_ad);

    for (int c = 0; c < CC; c++) {
        qpre_kernel<<<(BB * RR * CL) / 32, 96>>>(c, x);
        rnn_kernel<<<BB, 288>>>(c);
    }
    proj_kernel<<<(BB * CC * RR * CL) / 64, 256>>>(W_out, b_out, out);
}

// round 9
// speedup vs baseline: 1.9584x; 1.1640x over previous
#include <cuda_runtime.h>

#define BB 64
#define CC 3
#define RR 64
#define CL 64
#define EE 64
#define HH 32
#define LL 3
#define VV 258
#define GG 96   // 3*H

typedef unsigned long long u64;

// ---------------- scratch (device globals; no allocation) ----------------
__device__ float g_giemb[CC * VV * GG];                   // [c][v][g] = Wih0[:, :64] @ embed
__device__ float g_wpk[CC * 576 * 48];                    // per-thread packed half-rows: wi[16], wh[16], wq[16]
__device__ float g_bpk[CC * 576 * 4];                     // per-thread bias: (bi, bh, pv, 0)
__device__ float g_hid[(size_t)BB * CC * RR * CL * HH];   // all hidden outputs (~100 MB)

// ---------------- helpers ----------------
#define FMA2(acc, a, b) asm("fma.rn.f32x2 %0, %1, %2, %0;" : "+l"(acc) : "l"(a), "l"(b))

__device__ __forceinline__ float sum2p(u64 a, u64 b) {
    u64 s;
    asm("add.rn.f32x2 %0, %1, %2;" : "=l"(s) : "l"(a), "l"(b));
    float lo = __uint_as_float((unsigned)(s & 0xffffffffull));
    float hi = __uint_as_float((unsigned)(s >> 32));
    return lo + hi;
}
__device__ __forceinline__ void cpa16(void* dst, const void* src) {
    unsigned sd = (unsigned)__cvta_generic_to_shared(dst);
    asm volatile("cp.async.ca.shared.global [%0], [%1], 16;" :: "r"(sd), "l"(src) : "memory");
}
// sigmoid / tanh via MUFU.TANH (validated: rel_err ~1e-6 in R6/R8)
__device__ __forceinline__ float sigm_a(float x) {
    float t;
    asm("tanh.approx.f32 %0, %1;" : "=f"(t) : "f"(0.5f * x));
    return fmaf(0.5f, t, 0.5f);
}
__device__ __forceinline__ float tanh_a(float x) {
    float t;
    asm("tanh.approx.f32 %0, %1;" : "=f"(t) : "f"(x));
    return t;
}

// thread -> (layer, gate, half) mapping shared by prep and rnn kernels:
//   l = t/192; r192 = t%192; w6 = r192/32; lane = r192%32;
//   g = 16*w6 + (lane & 15);  hf = lane >> 4;
// Halves of the same gate sit in lanes k and k^16 of one warp (shfl_xor 16 reduce).
// Warps 0-3 of a group hold r,z gates (g<64); warps 4-5 hold n gates. Uniform branches.

// ---------------- precompute kernels ----------------
__global__ void prep_giemb(const float* __restrict__ Wih0, const float* __restrict__ embed) {
    int idx = blockIdx.x * blockDim.x + threadIdx.x;
    if (idx >= CC * VV * GG) return;
    int c = idx / (VV * GG);
    int rem = idx % (VV * GG);
    int v = rem / GG;
    int g = rem % GG;
    const float* wr = Wih0 + (c * GG + g) * (EE + 1);
    const float* em = embed + (c * VV + v) * EE;
    float acc = 0.f;
#pragma unroll
    for (int e = 0; e < EE; e++) acc += wr[e] * em[e];
    g_giemb[idx] = acc;
}

__global__ void prep_wpk3(const float* __restrict__ Wih0, const float* __restrict__ Wih_rest,
                          const float* __restrict__ Whh, const float* __restrict__ W_h2e,
                          const float* __restrict__ W_ad) {
    int idx = blockIdx.x * blockDim.x + threadIdx.x;
    if (idx >= CC * 576 * 48) return;
    int c = idx / (576 * 48);
    int rem = idx % (576 * 48);
    int t = rem / 48;
    int j = rem % 48;
    int side = j / 16, q = j % 16;
    int l = t / 192;
    int r192 = t % 192;
    int w6 = r192 >> 5, lane = r192 & 31;
    int g = (w6 << 4) | (lane & 15);
    int hf = lane >> 4;
    int e = hf * 16 + q;  // element within the 32-wide hidden vector
    float val = 0.f;
    if (side == 0) {
        if (l == 0) {
            const float* wr = Wih0 + (c * GG + g) * (EE + 1);
            for (int ee = 0; ee <= EE; ee++)
                val += wr[ee] * W_h2e[(c * (EE + 1) + ee) * HH + e];
        } else {
            val = Wih_rest[((c * (LL - 1) + (l - 1)) * GG + g) * HH + e];
        }
    } else if (side == 1) {
        val = Whh[((c * LL + l) * GG + g) * HH + e];
    } else {
        if (l == 0 && c > 0) {
            const float* wr = Wih0 + (c * GG + g) * (EE + 1);
            for (int ee = 0; ee <= EE; ee++)
                val += wr[ee] * W_ad[((c - 1) * (EE + 1) + ee) * HH + e];
        }
    }
    g_wpk[idx] = val;
}

__global__ void prep_bpk3(const float* __restrict__ Wih0, const float* __restrict__ bih,
                          const float* __restrict__ bhh, const float* __restrict__ b_h2e,
                          const float* __restrict__ b_ad) {
    int idx = blockIdx.x * blockDim.x + threadIdx.x;
    if (idx >= CC * 576) return;
    int c = idx / 576;
    int t = idx % 576;
    int l = t / 192;
    int r192 = t % 192;
    int w6 = r192 >> 5, lane = r192 & 31;
    int g = (w6 << 4) | (lane & 15);
    float bi, bh, pv;
    if (l == 0) {
        bi = bih[(c * LL + 0) * GG + g];
        const float* wr = Wih0 + (c * GG + g) * (EE + 1);
        for (int e = 0; e <= EE; e++) {
            float bb = b_h2e[c * (EE + 1) + e];
            if (c > 0) bb += b_ad[(c - 1) * (EE + 1) + e];
            bi += wr[e] * bb;
        }
        pv = Wih0[(c * GG + g) * (EE + 1) + EE];
    } else {
        bi = bih[(c * LL + l) * GG + g];
        pv = 0.f;
    }
    bh = bhh[(c * LL + l) * GG + g];
    g_bpk[idx * 4 + 0] = bi;
    g_bpk[idx * 4 + 1] = bh;
    g_bpk[idx * 4 + 2] = pv;
    g_bpk[idx * 4 + 3] = 0.f;
}

// ---------------- pipelined RNN kernel: 576 threads = 3 layer groups x 96 gates x 2 halves ----------------
__global__ void __launch_bounds__(576, 1) rnn_kernel(const int* __restrict__ x) {
    const int b = blockIdx.x;
    const int tid = threadIdx.x;
    const int l = tid / 192;            // layer group (warp-uniform)
    const int r192 = tid % 192;
    const int w6 = r192 >> 5;           // warp within group
    const int lane = r192 & 31;
    const int g = (w6 << 4) | (lane & 15);  // gate 0..95
    const int hf = lane >> 4;           // half 0/1 of the dot
    const bool isRZ = (w6 < 4);         // warp-uniform gate type
    const bool cellp = (r192 < 32);     // cell thread, unit u = lane
    const int u = lane;

    __shared__ __align__(16) float s_row[2][CL][HH];  // prev/cur row layer-2 outputs (row parity)
    __shared__ __align__(16) float s_pout[2][CL][HH]; // prev-channel outputs (double buffered)
    __shared__ __align__(16) float s_h[LL][HH];       // per-layer hidden
    __shared__ float s_rz[LL][64];                    // finished sigma(r), sigma(z)
    __shared__ __align__(8) float2 s_n2[LL][HH];      // (i_n, h_n)
    __shared__ __align__(16) int s_idx[2][CL];        // x indices (double buffered)

    for (int c = 0; c < CC; c++) {
        // per-thread packed half-rows (f32x2 pairs): wi, wh, wq — depth-4 FMA2 chains
        const ulonglong2* wv =
            reinterpret_cast<const ulonglong2*>(g_wpk + ((size_t)(c * 576 + tid)) * 48);
        ulonglong2 wi[4], wh[4], wq[4];
#pragma unroll
        for (int i = 0; i < 4; i++) wi[i] = wv[i];
#pragma unroll
        for (int i = 0; i < 4; i++) wh[i] = wv[4 + i];
#pragma unroll
        for (int i = 0; i < 4; i++) wq[i] = wv[8 + i];
        const float4 bias = reinterpret_cast<const float4*>(g_bpk)[c * 576 + tid];

        const float* giC = g_giemb + (size_t)c * VV * GG;
        const float* poutG = g_hid + (size_t)(b * CC + (c > 0 ? c - 1 : 0)) * (RR * CL * HH);
        float* hidG = g_hid + (size_t)(b * CC + c) * (RR * CL * HH);
        const int* xc = x + (size_t)(b * CC + c) * (RR * CL);

        // zero prev-row read buffer (row 0 reads zeros)
        for (int i = tid; i < CL * HH; i += 576) (&s_row[0][0][0])[i] = 0.f;

        // prefetch row 0 (pout + idx) into buffer 0
        if (c > 0) {
            const char* src = (const char*)poutG;
            char* dst = (char*)&s_pout[0][0][0];
            for (int i = tid; i < 512; i += 576) cpa16(dst + i * 16, src + i * 16);
        }
        if (tid < 16) cpa16((char*)&s_idx[0][0] + tid * 16, (const char*)xc + tid * 16);
        asm volatile("cp.async.commit_group;" ::: "memory");

        for (int r = 0; r < RR; r++) {
            const int rb = r & 1, wb = rb ^ 1;
            if (cellp) s_h[l][u] = 0.f;
            float ho = 0.f;

            // prefetch row r+1 into buffer wb
            if (r + 1 < RR) {
                if (c > 0) {
                    const char* src = (const char*)(poutG + (size_t)(r + 1) * CL * HH);
                    char* dst = (char*)&s_pout[wb][0][0];
                    for (int i = tid; i < 512; i += 576) cpa16(dst + i * 16, src + i * 16);
                }
                if (tid < 16)
                    cpa16((char*)&s_idx[wb][0] + tid * 16,
                          (const char*)(xc + (r + 1) * CL) + tid * 16);
            }
            asm volatile("cp.async.commit_group;" ::: "memory");
            asm volatile("cp.async.wait_group 1;" ::: "memory");
            __syncthreads();  // row r data + h reset visible

            const float pos = (float)r * (1.f / 32.f) - 1.f;
            const float bi0 = bias.x + bias.z * pos;
            float gie = 0.f;
            if (l == 0 && hf == 0) gie = giC[s_idx[rb][0] * GG + g];

            for (int s = 0; s < CL + LL - 1; s++) {
                const int t = s - l;  // warp-uniform
                const bool act = ((unsigned)t < (unsigned)CL);
                if (act) {
                    // h-side half-dot: Whh_l[g][hf*16:+16] . h_l[hf*16:+16]
                    u64 A0 = 0, A1 = 0;
                    const ulonglong2* hv =
                        reinterpret_cast<const ulonglong2*>(&s_h[l][0] + (hf << 4));
#pragma unroll
                    for (int i = 0; i < 4; i++) {
                        FMA2(A0, wh[i].x, hv[i].x);
                        FMA2(A1, wh[i].y, hv[i].y);
                    }
                    // input-side half-dot
                    const float* inb = (l == 0) ? &s_row[rb][t][0] : &s_h[l - 1][0];
                    const ulonglong2* iv =
                        reinterpret_cast<const ulonglong2*>(inb + (hf << 4));
                    u64 B0 = 0, B1 = 0;
#pragma unroll
                    for (int i = 0; i < 4; i++) {
                        FMA2(B0, wi[i].x, iv[i].x);
                        FMA2(B1, wi[i].y, iv[i].y);
                    }
                    if (l == 0 && c > 0) {  // channel-adapter half-dot
                        const ulonglong2* pv =
                            reinterpret_cast<const ulonglong2*>(&s_pout[rb][t][0] + (hf << 4));
#pragma unroll
                        for (int i = 0; i < 4; i++) {
                            FMA2(B0, wq[i].x, pv[i].x);
                            FMA2(B1, wq[i].y, pv[i].y);
                        }
                    }
                    float ph = sum2p(A0, A1);
                    float pi = sum2p(B0, B1);
                    // combine halves: lanes k <-> k^16 hold the two halves of gate g
                    pi += __shfl_xor_sync(0xffffffffu, pi, 16);
                    ph += __shfl_xor_sync(0xffffffffu, ph, 16);
                    if (hf == 0) {
                        float ah = ph + bias.y;
                        float ai = pi + ((l == 0) ? (bi0 + gie) : bias.x);
                        if (isRZ) s_rz[l][g] = sigm_a(ai + ah);
                        else s_n2[l][g - 64] = make_float2(ai, ah);
                    }
                }
                // prefetch next column's giemb gather (l0 half-0 threads)
                if (l == 0 && hf == 0 && s + 1 < CL) gie = giC[s_idx[rb][s + 1] * GG + g];
                __syncthreads();

                if (cellp && act) {  // GRU cell: unit u of layer l
                    float rg = s_rz[l][u];
                    float zg = s_rz[l][32 + u];
                    float2 nn = s_n2[l][u];
                    float ng = tanh_a(fmaf(rg, nn.y, nn.x));
                    float hn = fmaf(zg, ho - ng, ng);
                    ho = hn;
                    s_h[l][u] = hn;
                    if (l == 2) {
                        s_row[wb][t][u] = hn;                      // feeds next row
                        hidG[((size_t)r * CL + t) * HH + u] = hn;  // feeds next channel + projection
                    }
                }
                __syncthreads();
            }
        }
        __syncthreads();
    }
}

// ---------------- output projection with packed f32x2 FMA ----------------
__global__ void __launch_bounds__(256, 2) proj_kernel(const float* __restrict__ Wout,
                                                      const float* __restrict__ bout,
                                                      float* __restrict__ out) {
    __shared__ float Ws[32][264];  // Ws[k][v]
    __shared__ float hs[32][72];   // hs[k][p]
    __shared__ float bs[264];

    const int tid = threadIdx.x;
    const size_t p0 = (size_t)blockIdx.x * 64;

    for (int i = tid; i < VV * HH; i += 256) {
        int v = i >> 5, k = i & 31;
        Ws[k][v] = Wout[i];
    }
    if (tid < 256) bs[tid] = (tid < VV) ? bout[tid] : 0.f;
    if (tid < 2) bs[256 + tid] = bout[256 + tid];
    if (tid < 6) bs[258 + tid] = 0.f;
    {
        const float* hsrc = g_hid + p0 * HH;
        for (int i = tid; i < 64 * HH; i += 256) {
            int p = i >> 5, k = i & 31;
            hs[k][p] = hsrc[i];
        }
    }
    __syncthreads();

    const int tv = tid & 31;
    const int tp = tid >> 5;
    const int vb = tv * 8, pb = tp * 8;

    u64 acc[8][4];
#pragma unroll
    for (int pi = 0; pi < 8; pi++)
#pragma unroll
        for (int j = 0; j < 4; j++) acc[pi][j] = 0ull;

#pragma unroll 2
    for (int k = 0; k < 32; k++) {
        ulonglong2 w0 = *reinterpret_cast<const ulonglong2*>(&Ws[k][vb]);
        ulonglong2 w1 = *reinterpret_cast<const ulonglong2*>(&Ws[k][vb + 4]);
        float4 ha = *reinterpret_cast<const float4*>(&hs[k][pb]);
        float4 hb = *reinterpret_cast<const float4*>(&hs[k][pb + 4]);
        float hv[8] = {ha.x, ha.y, ha.z, ha.w, hb.x, hb.y, hb.z, hb.w};
#pragma unroll
        for (int pi = 0; pi < 8; pi++) {
            u64 hp;
            asm("mov.b64 %0, {%1, %1};" : "=l"(hp) : "f"(hv[pi]));
            FMA2(acc[pi][0], hp, w0.x);
            FMA2(acc[pi][1], hp, w0.y);
            FMA2(acc[pi][2], hp, w1.x);
            FMA2(acc[pi][3], hp, w1.y);
        }
    }

    ulonglong2 bz0 = *reinterpret_cast<const ulonglong2*>(&bs[vb]);
    ulonglong2 bz1 = *reinterpret_cast<const ulonglong2*>(&bs[vb + 4]);
    u64 bzv[4] = {bz0.x, bz0.y, bz1.x, bz1.y};

#pragma unroll
    for (int pi = 0; pi < 8; pi++) {
        size_t base = (p0 + pb + pi) * VV + vb;
#pragma unroll
        for (int j = 0; j < 4; j++) {
            u64 o;
            asm("add.rn.f32x2 %0, %1, %2;" : "=l"(o) : "l"(acc[pi][j]), "l"(bzv[j]));
            *reinterpret_cast<u64*>(&out[base + 2 * j]) = o;
        }
    }

    // tail columns v = 256, 257
    if (tid < 128) {
        int p = tid >> 1;
        int v = 256 + (tid & 1);
        float a = bs[v];
#pragma unroll
        for (int k = 0; k < 32; k++) a = fmaf(hs[k][p], Ws[k][v], a);
        out[(p0 + p) * VV + v] = a;
    }
}

// ---------------- launcher ----------------
extern "C" void kernel_launch(void* const* d_in, const int* in_sizes, int n_in,
                              void* d_out, int out_size) {
    const int* x = (const int*)d_in[0];
    const float* embed = (const float*)d_in[1];
    const float* Wih0 = (const float*)d_in[2];
    const float* Wih_rest = (const float*)d_in[3];
    const float* Whh = (const float*)d_in[4];
    const float* bih = (const float*)d_in[5];
    const float* bhh = (const float*)d_in[6];
    const float* W_h2e = (const float*)d_in[7];
    const float* b_h2e = (const float*)d_in[8];
    const float* W_ad = (const float*)d_in[9];
    const float* b_ad = (const float*)d_in[10];
    const float* W_out = (const float*)d_in[11];
    const float* b_out = (const float*)d_in[12];
    float* out = (float*)d_out;

    prep_giemb<<<(CC * VV * GG + 127) / 128, 128>>>(Wih0, embed);
    prep_wpk3<<<(CC * 576 * 48 + 127) / 128, 128>>>(Wih0, Wih_rest, Whh, W_h2e, W_ad);
    prep_bpk3<<<(CC * 576 + 127) / 128, 128>>>(Wih0, bih, bhh, b_h2e, b_ad);
    rnn_kernel<<<BB, 576>>>(x);
    proj_kernel<<<(BB * CC * RR * CL) / 64, 256>>>(W_out, b_out, out);
}

// round 11
// speedup vs baseline: 2.6828x; 1.3699x over previous
#include <cuda_runtime.h>

#define BB 64
#define CC 3
#define RR 64
#define CL 64
#define EE 64
#define HH 32
#define LL 3
#define VV 258
#define GG 96   // 3*H

typedef unsigned long long u64;

// ---------------- scratch (device globals; no allocation) ----------------
__device__ float g_giemb[CC * VV * GG];                   // [c][v][g] = Wih0[:, :64] @ embed
__device__ float g_wpk[CC * 288 * 96];                    // per-thread packed rows: wi[32], wh[32], wq[32]
__device__ float g_bpk[CC * 288 * 4];                     // per-thread bias: (bi, bh, pv, 0)
__device__ float g_hid[(size_t)BB * CC * RR * CL * HH];   // all hidden outputs (~100 MB)

// ---------------- helpers ----------------
#define FMA2(acc, a, b) asm("fma.rn.f32x2 %0, %1, %2, %0;" : "+l"(acc) : "l"(a), "l"(b))

__device__ __forceinline__ float sum2p(u64 a, u64 b) {
    u64 s;
    asm("add.rn.f32x2 %0, %1, %2;" : "=l"(s) : "l"(a), "l"(b));
    float lo = __uint_as_float((unsigned)(s & 0xffffffffull));
    float hi = __uint_as_float((unsigned)(s >> 32));
    return lo + hi;
}
__device__ __forceinline__ void cpa16(void* dst, const void* src) {
    unsigned sd = (unsigned)__cvta_generic_to_shared(dst);
    asm volatile("cp.async.ca.shared.global [%0], [%1], 16;" :: "r"(sd), "l"(src) : "memory");
}
__device__ __forceinline__ float sigm_a(float x) {
    float t;
    asm("tanh.approx.f32 %0, %1;" : "=f"(t) : "f"(0.5f * x));
    return fmaf(0.5f, t, 0.5f);
}
__device__ __forceinline__ float tanh_a(float x) {
    float t;
    asm("tanh.approx.f32 %0, %1;" : "=f"(t) : "f"(x));
    return t;
}

// ---------------- dynamic shared layout ----------------
struct SmemT {
    float hs0[RR][HH];       // layer-0 hidden per row
    float hs1[RR][HH];       // layer-1 hidden per row
    float hs2[RR + 1][HH];   // layer-2 hidden per row, +1 offset; [0] = zeros (row -1)
    float rz[LL][32][64];    // finished sigma(r), sigma(z) per (layer, slot=r&31)
    float2 n2[LL][32][HH];   // (i_n, h_n) pairs
    float pout[2][32][HH];   // prev-channel outputs, double-buffered by step parity
    int xs[RR * CL];         // whole channel's x indices
};

// ---------------- precompute kernels (R5 layouts, proven) ----------------
__global__ void prep_giemb(const float* __restrict__ Wih0, const float* __restrict__ embed) {
    int idx = blockIdx.x * blockDim.x + threadIdx.x;
    if (idx >= CC * VV * GG) return;
    int c = idx / (VV * GG);
    int rem = idx % (VV * GG);
    int v = rem / GG;
    int g = rem % GG;
    const float* wr = Wih0 + (c * GG + g) * (EE + 1);
    const float* em = embed + (c * VV + v) * EE;
    float acc = 0.f;
#pragma unroll
    for (int e = 0; e < EE; e++) acc += wr[e] * em[e];
    g_giemb[idx] = acc;
}

// Per (c, thread t in [0,288)): l = t/96, g = t%96. 96 floats:
//   [0:32)  wi : l==0 -> Wfh[g] (Wih0 @ W_h2e); l>=1 -> Wih_rest[c][l-1][g]
//   [32:64) wh : Whh[c][l][g]
//   [64:96) wq : l==0 && c>0 -> Wfad[g] (Wih0 @ W_ad); else 0
__global__ void prep_wpk2(const float* __restrict__ Wih0, const float* __restrict__ Wih_rest,
                          const float* __restrict__ Whh, const float* __restrict__ W_h2e,
                          const float* __restrict__ W_ad) {
    int idx = blockIdx.x * blockDim.x + threadIdx.x;
    if (idx >= CC * 288 * 96) return;
    int c = idx / (288 * 96);
    int rem = idx % (288 * 96);
    int t = rem / 96;
    int j = rem % 96;
    int s = j / 32;
    int k = j % 32;
    int l = t / 96;
    int g = t % 96;
    float val = 0.f;
    if (s == 0) {
        if (l == 0) {
            const float* wr = Wih0 + (c * GG + g) * (EE + 1);
            for (int e = 0; e <= EE; e++)
                val += wr[e] * W_h2e[(c * (EE + 1) + e) * HH + k];
        } else {
            val = Wih_rest[((c * (LL - 1) + (l - 1)) * GG + g) * HH + k];
        }
    } else if (s == 1) {
        val = Whh[((c * LL + l) * GG + g) * HH + k];
    } else {
        if (l == 0 && c > 0) {
            const float* wr = Wih0 + (c * GG + g) * (EE + 1);
            for (int e = 0; e <= EE; e++)
                val += wr[e] * W_ad[((c - 1) * (EE + 1) + e) * HH + k];
        }
    }
    g_wpk[idx] = val;
}

__global__ void prep_bpk2(const float* __restrict__ Wih0, const float* __restrict__ bih,
                          const float* __restrict__ bhh, const float* __restrict__ b_h2e,
                          const float* __restrict__ b_ad) {
    int idx = blockIdx.x * blockDim.x + threadIdx.x;
    if (idx >= CC * 288) return;
    int c = idx / 288;
    int t = idx % 288;
    int l = t / 96;
    int g = t % 96;
    float bi, bh, pv;
    if (l == 0) {
        bi = bih[(c * LL + 0) * GG + g];
        const float* wr = Wih0 + (c * GG + g) * (EE + 1);
        for (int e = 0; e <= EE; e++) {
            float bb = b_h2e[c * (EE + 1) + e];
            if (c > 0) bb += b_ad[(c - 1) * (EE + 1) + e];
            bi += wr[e] * bb;
        }
        pv = Wih0[(c * GG + g) * (EE + 1) + EE];
    } else {
        bi = bih[(c * LL + l) * GG + g];
        pv = 0.f;
    }
    bh = bhh[(c * LL + l) * GG + g];
    g_bpk[idx * 4 + 0] = bi;
    g_bpk[idx * 4 + 1] = bh;
    g_bpk[idx * 4 + 2] = pv;
    g_bpk[idx * 4 + 3] = 0.f;
}

// ---------------- wavefront RNN kernel ----------------
// Schedule: layer l of cell (r,t) runs at step s = 3r + t + l. All deps are step s-1.
// cp.async protocol (fixed): data for step s+1 is issued during step s's cell phase,
// committed, waited (wait_group 1), and PUBLISHED by the step-closing __syncthreads.
// Reads never precede a barrier that follows the issuing threads' wait.
__global__ void __launch_bounds__(288, 1) rnn_kernel(const int* __restrict__ x) {
    extern __shared__ __align__(16) char smem_raw[];
    SmemT* sm = reinterpret_cast<SmemT*>(smem_raw);

    const int b = blockIdx.x;
    const int tid = threadIdx.x;
    const int l = tid / 96;   // layer group (warp-uniform)
    const int g = tid % 96;   // gate
    const int u = g & 31;     // cell-phase unit
    const int ci0 = g >> 5;   // cell-phase cell offset

    for (int c = 0; c < CC; c++) {
        // per-thread packed weights (f32x2 pairs)
        const ulonglong2* wv =
            reinterpret_cast<const ulonglong2*>(g_wpk + ((size_t)(c * 288 + tid)) * 96);
        ulonglong2 wi[8], wh[8], wq[8];
#pragma unroll
        for (int i = 0; i < 8; i++) wi[i] = wv[i];
#pragma unroll
        for (int i = 0; i < 8; i++) wh[i] = wv[8 + i];
#pragma unroll
        for (int i = 0; i < 8; i++) wq[i] = wv[16 + i];
        const float4 bias = reinterpret_cast<const float4*>(g_bpk)[c * 288 + tid];

        const float* giC = g_giemb + (size_t)c * VV * GG;
        const float* poutG = g_hid + (size_t)(b * CC + (c > 0 ? c - 1 : 0)) * (RR * CL * HH);
        float* hidG = g_hid + (size_t)(b * CC + c) * (RR * CL * HH);
        const int* xc = x + (size_t)(b * CC + c) * (RR * CL);

        // zero hidden states (hs0,hs1,hs2 contiguous: (64+64+65)*32 floats)
        for (int i = tid; i < (RR + RR + RR + 1) * HH; i += 288) (&sm->hs0[0][0])[i] = 0.f;

        // pout prefetch: fill buf (m2&1) with pout values for layer-0 cells on line 3r+t = m2
        auto issue_pout = [&](int m2) {
            if (c == 0 || m2 > 252) return;
            int rlo = m2 > 61 ? (m2 - 61) / 3 : 0;
            int rhi = min(63, m2 / 3);
            int nch = (rhi - rlo + 1) << 3;
            if (l == 0) {
                for (int id = g; id < nch; id += 96) {
                    int ce = id >> 3, sub = id & 7;
                    int r = rlo + ce, t = m2 - 3 * r;
                    cpa16(&sm->pout[m2 & 1][r & 31][sub * 4],
                          poutG + ((size_t)(r * CL + t) * HH + sub * 4));
                }
            }
        };

        // prologue: whole-channel x + pout(0) in group 0; pout(1) in group 1
        for (int i = tid; i < (RR * CL) / 4; i += 288)
            cpa16((char*)&sm->xs[0] + i * 16, (const char*)xc + i * 16);
        issue_pout(0);
        asm volatile("cp.async.commit_group;" ::: "memory");
        issue_pout(1);
        asm volatile("cp.async.commit_group;" ::: "memory");
        asm volatile("cp.async.wait_group 1;" ::: "memory");  // xs + pout(0) landed (this thread)
        __syncthreads();                                       // ... and published to all threads

        for (int s = 0; s < 255; s++) {
            const int m = s - l;  // warp-uniform diagonal for this layer group
            const bool act = (m >= 0) && (m <= 252);
            int rlo = 0, rhi = -1;
            if (act) {
                rlo = m > 61 ? (m - 61) / 3 : 0;
                rhi = min(63, m / 3);
            }

            // ---------- gate phase ----------
            if (act) {
                if (l == 0) {
                    int p = rlo * CL + (m - 3 * rlo);
                    float qv = __ldg(giC + (size_t)sm->xs[p] * GG + g);
                    for (int r = rlo; r <= rhi; r++) {
                        float qn = 0.f;
                        if (r < rhi) qn = __ldg(giC + (size_t)sm->xs[p + 61] * GG + g);
                        u64 A0 = 0, A1 = 0, B0 = 0, B1 = 0;
                        const ulonglong2* hv = reinterpret_cast<const ulonglong2*>(&sm->hs0[r][0]);
                        const ulonglong2* iv = reinterpret_cast<const ulonglong2*>(&sm->hs2[r][0]);
#pragma unroll
                        for (int i = 0; i < 8; i++) {
                            FMA2(A0, wh[i].x, hv[i].x);
                            FMA2(A1, wh[i].y, hv[i].y);
                            FMA2(B0, wi[i].x, iv[i].x);
                            FMA2(B1, wi[i].y, iv[i].y);
                        }
                        if (c > 0) {
                            const ulonglong2* pv =
                                reinterpret_cast<const ulonglong2*>(&sm->pout[s & 1][r & 31][0]);
#pragma unroll
                            for (int i = 0; i < 8; i++) {
                                FMA2(B0, wq[i].x, pv[i].x);
                                FMA2(B1, wq[i].y, pv[i].y);
                            }
                        }
                        float ah = sum2p(A0, A1) + bias.y;
                        float pos = (float)r * (1.f / 32.f) - 1.f;
                        float ai = sum2p(B0, B1) + qv + fmaf(bias.z, pos, bias.x);
                        int slot = r & 31;
                        if (g < 64) sm->rz[0][slot][g] = sigm_a(ai + ah);
                        else sm->n2[0][slot][g - 64] = make_float2(ai, ah);
                        qv = qn;
                        p += 61;
                    }
                } else {
                    const float* hbase = (l == 1) ? &sm->hs1[0][0] : &sm->hs2[1][0];
                    const float* ibase = (l == 1) ? &sm->hs0[0][0] : &sm->hs1[0][0];
                    for (int r = rlo; r <= rhi; r++) {
                        u64 A0 = 0, A1 = 0, B0 = 0, B1 = 0;
                        const ulonglong2* hv =
                            reinterpret_cast<const ulonglong2*>(hbase + r * HH);
                        const ulonglong2* iv =
                            reinterpret_cast<const ulonglong2*>(ibase + r * HH);
#pragma unroll
                        for (int i = 0; i < 8; i++) {
                            FMA2(A0, wh[i].x, hv[i].x);
                            FMA2(A1, wh[i].y, hv[i].y);
                            FMA2(B0, wi[i].x, iv[i].x);
                            FMA2(B1, wi[i].y, iv[i].y);
                        }
                        float ah = sum2p(A0, A1) + bias.y;
                        float ai = sum2p(B0, B1) + bias.x;
                        int slot = r & 31;
                        if (g < 64) sm->rz[l][slot][g] = sigm_a(ai + ah);
                        else sm->n2[l][slot][g - 64] = make_float2(ai, ah);
                    }
                }
            }
            __syncthreads();

            // ---------- cell phase (+ pout prefetch for s+2, post-read) ----------
            if (act) {
                for (int r = rlo + ci0; r <= rhi; r += 3) {
                    int slot = r & 31;
                    int t = m - 3 * r;
                    float rg = sm->rz[l][slot][u];
                    float zg = sm->rz[l][slot][32 + u];
                    float2 nn = sm->n2[l][slot][u];
                    float ng = tanh_a(fmaf(rg, nn.y, nn.x));
                    float* hrow = (l == 0) ? &sm->hs0[r][0]
                                : (l == 1) ? &sm->hs1[r][0] : &sm->hs2[r + 1][0];
                    float hold = hrow[u];
                    float hn = fmaf(zg, hold - ng, ng);
                    hrow[u] = hn;
                    if (l == 2) hidG[(size_t)(r * CL + t) * HH + u] = hn;
                }
            }
            issue_pout(s + 2);  // writes buf (s&1): all gate-phase reads of it are pre-barrier
            asm volatile("cp.async.commit_group;" ::: "memory");
            asm volatile("cp.async.wait_group 1;" ::: "memory");  // pout(s+1) landed (this thread)
            __syncthreads();                                       // published for step s+1
        }
        __syncthreads();
    }
}

// ---------------- output projection with packed f32x2 FMA ----------------
__global__ void __launch_bounds__(256, 2) proj_kernel(const float* __restrict__ Wout,
                                                      const float* __restrict__ bout,
                                                      float* __restrict__ out) {
    __shared__ float Ws[32][264];  // Ws[k][v]
    __shared__ float hs[32][72];   // hs[k][p]
    __shared__ float bs[264];

    const int tid = threadIdx.x;
    const size_t p0 = (size_t)blockIdx.x * 64;

    for (int i = tid; i < VV * HH; i += 256) {
        int v = i >> 5, k = i & 31;
        Ws[k][v] = Wout[i];
    }
    if (tid < 256) bs[tid] = (tid < VV) ? bout[tid] : 0.f;
    if (tid < 2) bs[256 + tid] = bout[256 + tid];
    if (tid < 6) bs[258 + tid] = 0.f;
    {
        const float* hsrc = g_hid + p0 * HH;
        for (int i = tid; i < 64 * HH; i += 256) {
            int p = i >> 5, k = i & 31;
            hs[k][p] = hsrc[i];
        }
    }
    __syncthreads();

    const int tv = tid & 31;
    const int tp = tid >> 5;
    const int vb = tv * 8, pb = tp * 8;

    u64 acc[8][4];
#pragma unroll
    for (int pi = 0; pi < 8; pi++)
#pragma unroll
        for (int j = 0; j < 4; j++) acc[pi][j] = 0ull;

#pragma unroll 2
    for (int k = 0; k < 32; k++) {
        ulonglong2 w0 = *reinterpret_cast<const ulonglong2*>(&Ws[k][vb]);
        ulonglong2 w1 = *reinterpret_cast<const ulonglong2*>(&Ws[k][vb + 4]);
        float4 ha = *reinterpret_cast<const float4*>(&hs[k][pb]);
        float4 hb = *reinterpret_cast<const float4*>(&hs[k][pb + 4]);
        float hv[8] = {ha.x, ha.y, ha.z, ha.w, hb.x, hb.y, hb.z, hb.w};
#pragma unroll
        for (int pi = 0; pi < 8; pi++) {
            u64 hp;
            asm("mov.b64 %0, {%1, %1};" : "=l"(hp) : "f"(hv[pi]));
            FMA2(acc[pi][0], hp, w0.x);
            FMA2(acc[pi][1], hp, w0.y);
            FMA2(acc[pi][2], hp, w1.x);
            FMA2(acc[pi][3], hp, w1.y);
        }
    }

    ulonglong2 bz0 = *reinterpret_cast<const ulonglong2*>(&bs[vb]);
    ulonglong2 bz1 = *reinterpret_cast<const ulonglong2*>(&bs[vb + 4]);
    u64 bzv[4] = {bz0.x, bz0.y, bz1.x, bz1.y};

#pragma unroll
    for (int pi = 0; pi < 8; pi++) {
        size_t base = (p0 + pb + pi) * VV + vb;
#pragma unroll
        for (int j = 0; j < 4; j++) {
            u64 o;
            asm("add.rn.f32x2 %0, %1, %2;" : "=l"(o) : "l"(acc[pi][j]), "l"(bzv[j]));
            *reinterpret_cast<u64*>(&out[base + 2 * j]) = o;
        }
    }

    // tail columns v = 256, 257
    if (tid < 128) {
        int p = tid >> 1;
        int v = 256 + (tid & 1);
        float a = bs[v];
#pragma unroll
        for (int k = 0; k < 32; k++) a = fmaf(hs[k][p], Ws[k][v], a);
        out[(p0 + p) * VV + v] = a;
    }
}

// ---------------- launcher ----------------
extern "C" void kernel_launch(void* const* d_in, const int* in_sizes, int n_in,
                              void* d_out, int out_size) {
    const int* x = (const int*)d_in[0];
    const float* embed = (const float*)d_in[1];
    const float* Wih0 = (const float*)d_in[2];
    const float* Wih_rest = (const float*)d_in[3];
    const float* Whh = (const float*)d_in[4];
    const float* bih = (const float*)d_in[5];
    const float* bhh = (const float*)d_in[6];
    const float* W_h2e = (const float*)d_in[7];
    const float* b_h2e = (const float*)d_in[8];
    const float* W_ad = (const float*)d_in[9];
    const float* b_ad = (const float*)d_in[10];
    const float* W_out = (const float*)d_in[11];
    const float* b_out = (const float*)d_in[12];
    float* out = (float*)d_out;

    cudaFuncSetAttribute(rnn_kernel, cudaFuncAttributeMaxDynamicSharedMemorySize,
                         (int)sizeof(SmemT));

    prep_giemb<<<(CC * VV * GG + 127) / 128, 128>>>(Wih0, embed);
    prep_wpk2<<<(CC * 288 * 96 + 127) / 128, 128>>>(Wih0, Wih_rest, Whh, W_h2e, W_ad);
    prep_bpk2<<<(CC * 288 + 127) / 128, 128>>>(Wih0, bih, bhh, b_h2e, b_ad);
    rnn_kernel<<<BB, 288, sizeof(SmemT)>>>(x);
    proj_kernel<<<(BB * CC * RR * CL) / 64, 256>>>(W_out, b_out, out);
}